// round 13
// baseline (speedup 1.0000x reference)
#include <cuda_runtime.h>
#include <cuda_fp16.h>
#include <cstdint>
#include <cfloat>

// Problem constants
#define NROWS 65536   // 32 * 2048
#define DIMS  512
#define CODES 1024

#define MT   128      // rows per CTA (TC kernel)
#define NT2  256      // codes per tile
#define NCH  16       // 16 K-chunks of 32 floats
#define NGRP 8        // chunk pairs per N-tile
#define NTL  (CODES / NT2)   // 4 tiles

#define MARGIN 2.0e-4f       // ~9 sigma of fp16 top-2 score-difference error

// Scratch (device globals — allocation is forbidden)
__device__ float g_enorm[CODES];
__device__ float g_znorm[NROWS];
__device__ int   g_flagcnt;
__device__ int   g_flagrows[NROWS];
__device__ unsigned long long g_best[NROWS];
__device__ uint32_t g_e16[CODES * DIMS / 2];   // 1 MB fp16-packed emb

// ---------------------------------------------------------------------------
// Helpers
// ---------------------------------------------------------------------------
__device__ __forceinline__ void mma_f16(float* c,
                                        uint32_t a0, uint32_t a1, uint32_t a2, uint32_t a3,
                                        uint32_t b0, uint32_t b1) {
    asm volatile(
        "mma.sync.aligned.m16n8k16.row.col.f32.f16.f16.f32 "
        "{%0,%1,%2,%3}, {%4,%5,%6,%7}, {%8,%9}, {%0,%1,%2,%3};"
        : "+f"(c[0]), "+f"(c[1]), "+f"(c[2]), "+f"(c[3])
        : "r"(a0), "r"(a1), "r"(a2), "r"(a3), "r"(b0), "r"(b1));
}

__device__ __forceinline__ void ldsm_x4(uint32_t* f, uint32_t addr) {
    asm volatile(
        "ldmatrix.sync.aligned.m8n8.x4.shared.b16 {%0,%1,%2,%3}, [%4];"
        : "=r"(f[0]), "=r"(f[1]), "=r"(f[2]), "=r"(f[3]) : "r"(addr));
}

// byte offset of the 16B group (row r, u32-group g) in a swizzled [rows][16]-u32 tile
__device__ __forceinline__ uint32_t swz_grp(int r, int g) {
    int xr = (r >> 1) & 3;
    return (uint32_t)(((r << 4) + (((g ^ xr) & 3) << 2)) << 2);
}

__device__ __forceinline__ uint32_t pack_h2(float lo, float hi) {
    __half2 p = __float22half2_rn(make_float2(lo, hi));   // .x -> low 16 bits
    return *reinterpret_cast<uint32_t*>(&p);
}

// ---------------------------------------------------------------------------
// econv: emb fp32 -> packed fp16 global + ||e||^2 (fp64); resets flagcnt
// ---------------------------------------------------------------------------
__global__ void econv_kernel(const float* __restrict__ emb) {
    if (blockIdx.x == 0 && threadIdx.x == 0) g_flagcnt = 0;
    int warp = (blockIdx.x * blockDim.x + threadIdx.x) >> 5;
    int lane = threadIdx.x & 31;
    if (warp >= CODES) return;
    const float4* row = reinterpret_cast<const float4*>(emb + (size_t)warp * DIMS);
    double s = 0.0;
#pragma unroll
    for (int i = 0; i < 4; i++) {
        int j = lane + i * 32;
        float4 v = row[j];
        s += (double)v.x * v.x + (double)v.y * v.y
           + (double)v.z * v.z + (double)v.w * v.w;
        uint2 w = make_uint2(pack_h2(v.x, v.y), pack_h2(v.z, v.w));
        *reinterpret_cast<uint2*>(&g_e16[(size_t)warp * 256 + j * 2]) = w;
    }
#pragma unroll
    for (int off = 16; off > 0; off >>= 1)
        s += __shfl_xor_sync(0xffffffffu, s, off);
    if (lane == 0) g_enorm[warp] = (float)s;
}

// ---------------------------------------------------------------------------
// TC kernel: fused znorm + fp16-pack prologue, A resident, B 2-chunk dbuf
// 512 threads: 16 warps = 2 (M: 64 rows) x 8 (N: 32 codes)
// Dynamic smem: A = 16 x 8KB = 128KB; B dbuf = 2 x 32KB at +128KB
// ---------------------------------------------------------------------------
#define SM_A_BYTES (NCH * 8192)              // 131072
#define SM_DYN     (SM_A_BYTES + 2 * 32768)  // 196608

extern __shared__ uint32_t dsm[];

__global__ __launch_bounds__(512, 1)
void vq_mma_kernel(const float* __restrict__ z,
                   const float* __restrict__ emb,
                   float* __restrict__ out) {
    __shared__ float znr[128];
    __shared__ float sen[NT2];
    __shared__ float sbest[128 * 8];
    __shared__ float sb2  [128 * 8];
    __shared__ int   sidn [128 * 8];
    __shared__ int   srow [128];

    const int t    = threadIdx.x;
    const int lane = t & 31;
    const int wid  = t >> 5;
    const int row0 = blockIdx.x * MT;
    const int wm   = (wid & 1) * 64;
    const int wcol = wid >> 1;          // 0..7
    const int wn   = wcol * 32;
    const int lr4  = lane >> 2;
    const int lc   = lane & 3;

    const int m8 = lane >> 3, l7 = lane & 7;
    const int arow_off = ((m8 & 1) << 3) + l7;
    const int ag_off   = m8 >> 1;
    const int brow     = wn + ((m8 >> 1) << 3) + l7;
    const int bg_off   = m8 & 1;

    const uint32_t sAb = (uint32_t)__cvta_generic_to_shared(dsm);
    const uint32_t sBb = sAb + SM_A_BYTES;

    const int sr = t >> 2, sg = t & 3;
    const uint32_t stsB0 = swz_grp(sr, sg);
    const uint32_t stsB1 = swz_grp(sr + 128, sg);

    for (int i = t; i < 128 * 8; i += 512) {
        sbest[i] = FLT_MAX; sb2[i] = FLT_MAX; sidn[i] = 0;
    }

    // ---- fused prologue: read z fp32 ONCE -> fp64 znorm + pack into resident A ----
    {
        char* sAc = reinterpret_cast<char*>(dsm);
#pragma unroll
        for (int rr = 0; rr < 8; rr++) {
            int row = wid * 8 + rr;
            const float4* rp = reinterpret_cast<const float4*>(
                z + (size_t)(row0 + row) * DIMS);
            double s = 0.0;
#pragma unroll
            for (int i = 0; i < 4; i++) {
                int j = lane + i * 32;            // float4 index 0..127
                float4 v = rp[j];
                s += (double)v.x * v.x + (double)v.y * v.y
                   + (double)v.z * v.z + (double)v.w * v.w;
                int c = j >> 3;                   // chunk 0..15
                uint32_t boff = swz_grp(row, (j >> 1) & 3) + (uint32_t)((j & 1) << 3);
                uint2 w = make_uint2(pack_h2(v.x, v.y), pack_h2(v.z, v.w));
                *reinterpret_cast<uint2*>(sAc + c * 8192 + boff) = w;
            }
#pragma unroll
            for (int sh = 16; sh > 0; sh >>= 1)
                s += __shfl_xor_sync(0xffffffffu, s, sh);
            if (lane == 0) { znr[row] = (float)s; g_znorm[row0 + row] = (float)s; }
        }
    }
    __syncthreads();

    char* sBc = reinterpret_cast<char*>(dsm) + SM_A_BYTES;

    for (int nt = 0; nt < NTL; nt++) {
        const int n0 = nt * NT2;
        if (t < NT2 / 4)
            reinterpret_cast<float4*>(sen)[t] =
                reinterpret_cast<const float4*>(&g_enorm[n0])[t];

        float acc[4][4][4];
#pragma unroll
        for (int mi = 0; mi < 4; mi++)
#pragma unroll
            for (int nj = 0; nj < 4; nj++)
#pragma unroll
                for (int q = 0; q < 4; q++) acc[mi][nj][q] = 0.f;

        const uint32_t* bsrc0 = &g_e16[(size_t)(n0 + sr) * 256 + sg * 4];
        const uint32_t* bsrc1 = bsrc0 + 128 * 256;

        // stage group 0 (chunks 0,1) into buffer 0
        uint4 pb[4];
        pb[0] = *reinterpret_cast<const uint4*>(bsrc0);
        pb[1] = *reinterpret_cast<const uint4*>(bsrc1);
        pb[2] = *reinterpret_cast<const uint4*>(bsrc0 + 16);
        pb[3] = *reinterpret_cast<const uint4*>(bsrc1 + 16);
        *reinterpret_cast<uint4*>(sBc + stsB0)         = pb[0];
        *reinterpret_cast<uint4*>(sBc + stsB1)         = pb[1];
        *reinterpret_cast<uint4*>(sBc + 16384 + stsB0) = pb[2];
        *reinterpret_cast<uint4*>(sBc + 16384 + stsB1) = pb[3];
        __syncthreads();

        for (int g = 0; g < NGRP; g++) {
            const int cur = g & 1;
            if (g + 1 < NGRP) {
                pb[0] = *reinterpret_cast<const uint4*>(bsrc0 + (2 * g + 2) * 16);
                pb[1] = *reinterpret_cast<const uint4*>(bsrc1 + (2 * g + 2) * 16);
                pb[2] = *reinterpret_cast<const uint4*>(bsrc0 + (2 * g + 3) * 16);
                pb[3] = *reinterpret_cast<const uint4*>(bsrc1 + (2 * g + 3) * 16);
            }

            const uint32_t bufB = sBb + cur * 32768;
#pragma unroll
            for (int kk = 0; kk < 4; kk++) {            // chunk 2g+(kk>>1), ks = kk&1
                const uint32_t bA = sAb + (2 * g + (kk >> 1)) * 8192;
                const uint32_t bB = bufB + (kk >> 1) * 16384;
                const int ks = kk & 1;
                uint32_t B0[4], B1[4];
                ldsm_x4(B0, bB + swz_grp(brow,      2 * ks + bg_off));
                ldsm_x4(B1, bB + swz_grp(brow + 16, 2 * ks + bg_off));
#pragma unroll
                for (int mi = 0; mi < 4; mi++) {
                    uint32_t A[4];
                    ldsm_x4(A, bA + swz_grp(wm + mi * 16 + arow_off, 2 * ks + ag_off));
                    mma_f16(acc[mi][0], A[0], A[1], A[2], A[3], B0[0], B0[1]);
                    mma_f16(acc[mi][1], A[0], A[1], A[2], A[3], B0[2], B0[3]);
                    mma_f16(acc[mi][2], A[0], A[1], A[2], A[3], B1[0], B1[1]);
                    mma_f16(acc[mi][3], A[0], A[1], A[2], A[3], B1[2], B1[3]);
                }
            }

            if (g + 1 < NGRP) {
                char* nbuf = sBc + (cur ^ 1) * 32768;
                *reinterpret_cast<uint4*>(nbuf + stsB0)         = pb[0];
                *reinterpret_cast<uint4*>(nbuf + stsB1)         = pb[1];
                *reinterpret_cast<uint4*>(nbuf + 16384 + stsB0) = pb[2];
                *reinterpret_cast<uint4*>(nbuf + 16384 + stsB1) = pb[3];
            }
            __syncthreads();
        }

        // ---- epilogue: ref-rounding score + tile top-2 + smem merge ----
#pragma unroll
        for (int mi = 0; mi < 4; mi++) {
#pragma unroll
            for (int h = 0; h < 2; h++) {
                int row = wm + mi * 16 + lr4 + 8 * h;
                float znv = znr[row];
                float b = FLT_MAX, b2v = FLT_MAX;
                int   bi = 0;
#pragma unroll
                for (int nj = 0; nj < 4; nj++) {
                    int ce = wn + nj * 8 + 2 * lc;
                    float en0 = sen[ce], en1 = sen[ce + 1];
                    float s0 = __fsub_rn(__fadd_rn(znv, en0), __fmul_rn(2.0f, acc[mi][nj][h * 2]));
                    float s1 = __fsub_rn(__fadd_rn(znv, en1), __fmul_rn(2.0f, acc[mi][nj][h * 2 + 1]));
                    int cb = n0 + ce;
                    if (s0 < b) { b2v = b; b = s0; bi = cb; }
                    else if (s0 < b2v) b2v = s0;
                    if (s1 < b) { b2v = b; b = s1; bi = cb + 1; }
                    else if (s1 < b2v) b2v = s1;
                }
#pragma unroll
                for (int off = 1; off <= 2; off <<= 1) {
                    float vb  = __shfl_xor_sync(0xffffffffu, b,   off);
                    float vb2 = __shfl_xor_sync(0xffffffffu, b2v, off);
                    int   vi  = __shfl_xor_sync(0xffffffffu, bi,  off);
                    if (vb < b) { b2v = fminf(b, vb2); b = vb; bi = vi; }
                    else if (vb > b) { b2v = fminf(b2v, vb); }
                    else { bi = min(bi, vi); b2v = vb; }
                }
                if (lc == 0) {
                    int s = row * 8 + wcol;
                    float ob = sbest[s], ob2 = sb2[s];
                    int   oi = sidn[s];
                    if (b < ob)      { sbest[s] = b;  sb2[s] = fminf(ob, b2v);  sidn[s] = bi; }
                    else if (b > ob) {                sb2[s] = fminf(ob2, b);                 }
                    else             {                sb2[s] = ob;              sidn[s] = min(oi, bi); }
                }
            }
        }
        __syncthreads();
    }

    // ---- final per-row merge + flag ----
    if (t < 128) {
        float b  = sbest[t * 8];
        float bb = sb2  [t * 8];
        int   bi = sidn [t * 8];
#pragma unroll
        for (int x = 1; x < 8; x++) {
            float v  = sbest[t * 8 + x];
            float v2 = sb2  [t * 8 + x];
            int   vi = sidn [t * 8 + x];
            if (v < b) { bb = fminf(b, v2); b = v; bi = vi; }
            else if (v > b) { bb = fminf(bb, v); }
            else { bi = min(bi, vi); bb = v; }
        }
        srow[t] = bi;
        if (__fsub_rn(bb, b) < MARGIN) {
            int row = row0 + t;
            g_best[row] = ~0ULL;
            int p = atomicAdd(&g_flagcnt, 1);
            g_flagrows[p] = row;
        }
    }
    __syncthreads();

    // ---- gather ----
    float4*       out4 = reinterpret_cast<float4*>(out + (size_t)row0 * DIMS);
    const float4* emb4 = reinterpret_cast<const float4*>(emb);
    for (int v = t; v < 128 * (DIMS / 4); v += 512) {
        int r  = v >> 7;
        int c4 = v & 127;
        out4[(size_t)r * 128 + c4] = emb4[(size_t)srow[r] * 128 + c4];
    }
}

// ---------------------------------------------------------------------------
// Exact fallback: R2-identical ascending-k fmaf chains for flagged rows.
// Task = 128 rows x 64 codes (R12-proven shape)
// ---------------------------------------------------------------------------
__global__ __launch_bounds__(256)
void vq_exact_kernel(const float* __restrict__ z,
                     const float* __restrict__ emb) {
    __shared__ float Zs[16 * 128];
    __shared__ float Es[16 * 64];
    __shared__ int   rlist[128];

    const int t  = threadIdx.x;
    const int tx = t & 15;    // 4 codes each
    const int ty = t >> 4;    // 8 rows each
    const int lr = t >> 2;    // staging row 0..63 (and +64)
    const int dq = t & 3;

    int cnt = g_flagcnt;
    if (cnt <= 0) return;
    int tb = (cnt + 127) >> 7;
    int total = tb * 16;

    for (int task = blockIdx.x; task < total; task += gridDim.x) {
        int rb = task >> 4;
        int cg = task & 15;
        int c0 = cg * 64;

        __syncthreads();
        if (t < 128) {
            int j = rb * 128 + t;
            rlist[t] = g_flagrows[j < cnt ? j : cnt - 1];
        }
        __syncthreads();

        int rows[8]; float zn[8];
#pragma unroll
        for (int i = 0; i < 8; i++) {
            rows[i] = rlist[ty * 8 + i];
            zn[i] = g_znorm[rows[i]];
        }
        float en[4];
#pragma unroll
        for (int j = 0; j < 4; j++) en[j] = g_enorm[c0 + tx * 4 + j];

        float acc[8][4];
#pragma unroll
        for (int i = 0; i < 8; i++)
#pragma unroll
            for (int j = 0; j < 4; j++) acc[i][j] = 0.f;

        for (int c = 0; c < 32; c++) {       // 32 x 16-float chunks, R2 ordering
            const int k0 = c * 16;
            float4 za = *reinterpret_cast<const float4*>(
                z + (size_t)rlist[lr] * DIMS + k0 + dq * 4);
            float4 zb = *reinterpret_cast<const float4*>(
                z + (size_t)rlist[lr + 64] * DIMS + k0 + dq * 4);
            __syncthreads();
            Zs[(dq * 4 + 0) * 128 + lr] = za.x;
            Zs[(dq * 4 + 1) * 128 + lr] = za.y;
            Zs[(dq * 4 + 2) * 128 + lr] = za.z;
            Zs[(dq * 4 + 3) * 128 + lr] = za.w;
            Zs[(dq * 4 + 0) * 128 + lr + 64] = zb.x;
            Zs[(dq * 4 + 1) * 128 + lr + 64] = zb.y;
            Zs[(dq * 4 + 2) * 128 + lr + 64] = zb.z;
            Zs[(dq * 4 + 3) * 128 + lr + 64] = zb.w;
            if (t < 256) {   // stage E: 64 codes x 16 K = 256 float4
                int r = t >> 2, q = t & 3;
                float4 x = *reinterpret_cast<const float4*>(
                    emb + (size_t)(c0 + r) * DIMS + k0 + q * 4);
                Es[(q * 4 + 0) * 64 + r] = x.x;
                Es[(q * 4 + 1) * 64 + r] = x.y;
                Es[(q * 4 + 2) * 64 + r] = x.z;
                Es[(q * 4 + 3) * 64 + r] = x.w;
            }
            __syncthreads();

#pragma unroll
            for (int k = 0; k < 16; k++) {
                float zf[8], ef[4];
                *reinterpret_cast<float4*>(zf)     = *reinterpret_cast<float4*>(&Zs[k * 128 + ty * 8]);
                *reinterpret_cast<float4*>(zf + 4) = *reinterpret_cast<float4*>(&Zs[k * 128 + ty * 8 + 4]);
                *reinterpret_cast<float4*>(ef)     = *reinterpret_cast<float4*>(&Es[k * 64 + tx * 4]);
#pragma unroll
                for (int i = 0; i < 8; i++)
#pragma unroll
                    for (int j = 0; j < 4; j++)
                        acc[i][j] = fmaf(zf[i], ef[j], acc[i][j]);
            }
        }

        // score + per-thread argmin + cross-lane packed min (tie -> lowest idx)
#pragma unroll
        for (int i = 0; i < 8; i++) {
            float bb = 3.4e38f;
            int   bi = 0;
#pragma unroll
            for (int j = 0; j < 4; j++) {
                float s = __fsub_rn(__fadd_rn(zn[i], en[j]),
                                    __fmul_rn(2.0f, acc[i][j]));
                if (s < bb) { bb = s; bi = c0 + tx * 4 + j; }
            }
            unsigned long long pk =
                ((unsigned long long)__float_as_uint(bb) << 32) | (unsigned)bi;
#pragma unroll
            for (int off = 1; off <= 8; off <<= 1) {
                unsigned long long o = __shfl_xor_sync(0xffffffffu, pk, off);
                if (o < pk) pk = o;
            }
            if (tx == 0) atomicMin(&g_best[rows[i]], pk);
        }
    }
}

// ---------------------------------------------------------------------------
// Fixup gather for flagged rows
// ---------------------------------------------------------------------------
__global__ void vq_fix_kernel(const float* __restrict__ emb,
                              float* __restrict__ out) {
    int cnt = g_flagcnt;
    for (int j = blockIdx.x; j < cnt; j += gridDim.x) {
        int row = g_flagrows[j];
        unsigned idx = (unsigned)(g_best[row] & 0xffffffffu);
        const float4* src = reinterpret_cast<const float4*>(emb + (size_t)idx * DIMS);
        float4*       dst = reinterpret_cast<float4*>(out + (size_t)row * DIMS);
        for (int v = threadIdx.x; v < DIMS / 4; v += blockDim.x)
            dst[v] = src[v];
    }
}

// ---------------------------------------------------------------------------
// Launch
// ---------------------------------------------------------------------------
extern "C" void kernel_launch(void* const* d_in, const int* in_sizes, int n_in,
                              void* d_out, int out_size) {
    const float* z   = (const float*)d_in[0];   // [32,2048,512] fp32
    const float* emb = (const float*)d_in[1];   // [1024,512] fp32
    float* out = (float*)d_out;

    cudaFuncSetAttribute(vq_mma_kernel,
                         cudaFuncAttributeMaxDynamicSharedMemorySize, SM_DYN);

    econv_kernel<<<(CODES * 32 + 255) / 256, 256>>>(emb);   // also resets flagcnt
    vq_mma_kernel<<<NROWS / MT, 512, SM_DYN>>>(z, emb, out);
    vq_exact_kernel<<<1024, 256>>>(z, emb);
    vq_fix_kernel<<<1024, 128>>>(emb, out);
}

// round 14
// speedup vs baseline: 1.0135x; 1.0135x over previous
#include <cuda_runtime.h>
#include <cuda_fp16.h>
#include <cstdint>
#include <cfloat>

// Problem constants
#define NROWS 65536   // 32 * 2048
#define DIMS  512
#define CODES 1024

#define MT   64       // rows per CTA (TC kernel)
#define NT2  256      // codes per tile
#define NCH  16       // K-chunks of 32 floats
#define NTL  (CODES / NT2)   // 4 tiles

#define MARGIN 2.0e-4f       // ~13 sigma of fp16 score error

// Scratch (device globals — allocation is forbidden)
__device__ float g_enorm[CODES];
__device__ float g_znorm[NROWS];
__device__ int   g_flagcnt;
__device__ int   g_flagrows[NROWS];
__device__ unsigned long long g_best[NROWS];
__device__ uint32_t g_z16[NROWS * DIMS / 2];   // 64 MB fp16-packed z
__device__ uint32_t g_e16[CODES * DIMS / 2];   // 1 MB fp16-packed emb

// ---------------------------------------------------------------------------
// Helpers
// ---------------------------------------------------------------------------
__device__ __forceinline__ void mma_f16(float* c,
                                        uint32_t a0, uint32_t a1, uint32_t a2, uint32_t a3,
                                        uint32_t b0, uint32_t b1) {
    asm volatile(
        "mma.sync.aligned.m16n8k16.row.col.f32.f16.f16.f32 "
        "{%0,%1,%2,%3}, {%4,%5,%6,%7}, {%8,%9}, {%0,%1,%2,%3};"
        : "+f"(c[0]), "+f"(c[1]), "+f"(c[2]), "+f"(c[3])
        : "r"(a0), "r"(a1), "r"(a2), "r"(a3), "r"(b0), "r"(b1));
}

__device__ __forceinline__ void ldsm_x4(uint32_t* f, uint32_t addr) {
    asm volatile(
        "ldmatrix.sync.aligned.m8n8.x4.shared.b16 {%0,%1,%2,%3}, [%4];"
        : "=r"(f[0]), "=r"(f[1]), "=r"(f[2]), "=r"(f[3]) : "r"(addr));
}

// byte offset of the 16B group (row r, u32-group g) in a swizzled [rows][16]-u32 tile
__device__ __forceinline__ uint32_t swz_grp(int r, int g) {
    int xr = (r >> 1) & 3;
    return (uint32_t)(((r << 4) + (((g ^ xr) & 3) << 2)) << 2);
}

__device__ __forceinline__ uint32_t pack_h2(float lo, float hi) {
    __half2 p = __float22half2_rn(make_float2(lo, hi));   // .x -> low 16 bits
    return *reinterpret_cast<uint32_t*>(&p);
}

// ---------------------------------------------------------------------------
// Convert kernels: fp32 -> packed fp16 globals, fused fp64 norms (R12-proven)
// ---------------------------------------------------------------------------
__global__ void econv_kernel(const float* __restrict__ emb) {
    if (blockIdx.x == 0 && threadIdx.x == 0) g_flagcnt = 0;
    int warp = (blockIdx.x * blockDim.x + threadIdx.x) >> 5;
    int lane = threadIdx.x & 31;
    if (warp >= CODES) return;
    const float4* row = reinterpret_cast<const float4*>(emb + (size_t)warp * DIMS);
    double s = 0.0;
#pragma unroll
    for (int i = 0; i < 4; i++) {
        int j = lane + i * 32;
        float4 v = row[j];
        s += (double)v.x * v.x + (double)v.y * v.y
           + (double)v.z * v.z + (double)v.w * v.w;
        uint2 w = make_uint2(pack_h2(v.x, v.y), pack_h2(v.z, v.w));
        *reinterpret_cast<uint2*>(&g_e16[(size_t)warp * 256 + j * 2]) = w;
    }
#pragma unroll
    for (int off = 16; off > 0; off >>= 1)
        s += __shfl_xor_sync(0xffffffffu, s, off);
    if (lane == 0) g_enorm[warp] = (float)s;
}

__global__ void zconv_kernel(const float* __restrict__ z) {
    int warp = (blockIdx.x * blockDim.x + threadIdx.x) >> 5;
    int lane = threadIdx.x & 31;
    if (warp >= NROWS) return;
    const float4* row = reinterpret_cast<const float4*>(z + (size_t)warp * DIMS);
    double s = 0.0;
#pragma unroll
    for (int i = 0; i < 4; i++) {
        int j = lane + i * 32;
        float4 v = row[j];
        s += (double)v.x * v.x + (double)v.y * v.y
           + (double)v.z * v.z + (double)v.w * v.w;
        uint2 w = make_uint2(pack_h2(v.x, v.y), pack_h2(v.z, v.w));
        *reinterpret_cast<uint2*>(&g_z16[(size_t)warp * 256 + j * 2]) = w;
    }
#pragma unroll
    for (int off = 16; off > 0; off >>= 1)
        s += __shfl_xor_sync(0xffffffffu, s, off);
    if (lane == 0) g_znorm[warp] = (float)s;
}

// ---------------------------------------------------------------------------
// TC kernel: fp16 mma.sync (k16), MT=64, 256 threads, 2 CTAs/SM
// 8 warps, each owns all 64 rows x 32 codes (same warp shape as R12)
// Dynamic smem: A = 16 x 4KB = 64KB; B dbuf = 2 x 16KB at +64KB
// ---------------------------------------------------------------------------
#define SM_A_BYTES (NCH * 4096)              // 65536
#define SM_DYN     (SM_A_BYTES + 2 * 16384)  // 98304

extern __shared__ uint32_t dsm[];

__global__ __launch_bounds__(256, 2)
void vq_mma_kernel(const float* __restrict__ emb,
                   float* __restrict__ out) {
    __shared__ float znr[MT];
    __shared__ float sen[NT2];
    __shared__ float sbest[MT * 8];
    __shared__ float sb2  [MT * 8];
    __shared__ int   sidn [MT * 8];
    __shared__ int   srow [MT];

    const int t    = threadIdx.x;
    const int lane = t & 31;
    const int wid  = t >> 5;            // 0..7
    const int row0 = blockIdx.x * MT;
    const int wn   = wid * 32;
    const int lr4  = lane >> 2;
    const int lc   = lane & 3;

    const int m8 = lane >> 3, l7 = lane & 7;
    const int arow_off = ((m8 & 1) << 3) + l7;   // + mi*16
    const int ag_off   = m8 >> 1;
    const int brow     = wn + ((m8 >> 1) << 3) + l7;
    const int bg_off   = m8 & 1;

    const uint32_t sAb = (uint32_t)__cvta_generic_to_shared(dsm);
    const uint32_t sBb = sAb + SM_A_BYTES;

    const int sr = t >> 2, sg = t & 3;           // sr 0..63
    const uint32_t stsA = swz_grp(sr, sg);
    uint32_t stsB[4];
#pragma unroll
    for (int i = 0; i < 4; i++) stsB[i] = swz_grp(sr + 64 * i, sg);

    for (int i = t; i < MT * 8; i += 256) {
        sbest[i] = FLT_MAX; sb2[i] = FLT_MAX; sidn[i] = 0;
    }
    if (t < MT) znr[t] = g_znorm[row0 + t];

    // ---- load resident A: 16 chunk-tiles of 4KB, 1 uint4 per thread each ----
    {
        const uint32_t* zsrc = &g_z16[(size_t)(row0 + sr) * 256 + sg * 4];
        char* sAc = reinterpret_cast<char*>(dsm);
#pragma unroll
        for (int c = 0; c < NCH; c++) {
            uint4 v = *reinterpret_cast<const uint4*>(zsrc + c * 16);
            *reinterpret_cast<uint4*>(sAc + c * 4096 + stsA) = v;
        }
    }
    __syncthreads();

    char* sBc = reinterpret_cast<char*>(dsm) + SM_A_BYTES;

    for (int nt = 0; nt < NTL; nt++) {
        const int n0 = nt * NT2;
        if (t < NT2 / 4)
            reinterpret_cast<float4*>(sen)[t] =
                reinterpret_cast<const float4*>(&g_enorm[n0])[t];

        float acc[4][4][4];
#pragma unroll
        for (int mi = 0; mi < 4; mi++)
#pragma unroll
            for (int nj = 0; nj < 4; nj++)
#pragma unroll
                for (int q = 0; q < 4; q++) acc[mi][nj][q] = 0.f;

        const uint32_t* bsrc[4];
#pragma unroll
        for (int i = 0; i < 4; i++)
            bsrc[i] = &g_e16[(size_t)(n0 + sr + 64 * i) * 256 + sg * 4];

        // stage B chunk 0 into buffer 0
        uint4 pb[4];
#pragma unroll
        for (int i = 0; i < 4; i++) pb[i] = *reinterpret_cast<const uint4*>(bsrc[i]);
#pragma unroll
        for (int i = 0; i < 4; i++)
            *reinterpret_cast<uint4*>(sBc + stsB[i]) = pb[i];
        __syncthreads();

        for (int c = 0; c < NCH; c++) {
            const int cur = c & 1;
            if (c + 1 < NCH) {
#pragma unroll
                for (int i = 0; i < 4; i++)
                    pb[i] = *reinterpret_cast<const uint4*>(bsrc[i] + (c + 1) * 16);
            }

            const uint32_t bufA = sAb + c * 4096;
            const uint32_t bufB = sBb + cur * 16384;
#pragma unroll
            for (int ks = 0; ks < 2; ks++) {
                uint32_t B0[4], B1[4];
                ldsm_x4(B0, bufB + swz_grp(brow,      2 * ks + bg_off));
                ldsm_x4(B1, bufB + swz_grp(brow + 16, 2 * ks + bg_off));
#pragma unroll
                for (int mi = 0; mi < 4; mi++) {
                    uint32_t A[4];
                    ldsm_x4(A, bufA + swz_grp(mi * 16 + arow_off, 2 * ks + ag_off));
                    mma_f16(acc[mi][0], A[0], A[1], A[2], A[3], B0[0], B0[1]);
                    mma_f16(acc[mi][1], A[0], A[1], A[2], A[3], B0[2], B0[3]);
                    mma_f16(acc[mi][2], A[0], A[1], A[2], A[3], B1[0], B1[1]);
                    mma_f16(acc[mi][3], A[0], A[1], A[2], A[3], B1[2], B1[3]);
                }
            }

            if (c + 1 < NCH) {
                char* nbuf = sBc + (cur ^ 1) * 16384;
#pragma unroll
                for (int i = 0; i < 4; i++)
                    *reinterpret_cast<uint4*>(nbuf + stsB[i]) = pb[i];
            }
            __syncthreads();
        }

        // ---- epilogue: ref-rounding score + tile top-2 + smem merge ----
#pragma unroll
        for (int mi = 0; mi < 4; mi++) {
#pragma unroll
            for (int h = 0; h < 2; h++) {
                int row = mi * 16 + lr4 + 8 * h;
                float znv = znr[row];
                float b = FLT_MAX, b2v = FLT_MAX;
                int   bi = 0;
#pragma unroll
                for (int nj = 0; nj < 4; nj++) {
                    int ce = wn + nj * 8 + 2 * lc;
                    float en0 = sen[ce], en1 = sen[ce + 1];
                    float s0 = __fsub_rn(__fadd_rn(znv, en0), __fmul_rn(2.0f, acc[mi][nj][h * 2]));
                    float s1 = __fsub_rn(__fadd_rn(znv, en1), __fmul_rn(2.0f, acc[mi][nj][h * 2 + 1]));
                    int cb = n0 + ce;
                    if (s0 < b) { b2v = b; b = s0; bi = cb; }
                    else if (s0 < b2v) b2v = s0;
                    if (s1 < b) { b2v = b; b = s1; bi = cb + 1; }
                    else if (s1 < b2v) b2v = s1;
                }
#pragma unroll
                for (int off = 1; off <= 2; off <<= 1) {
                    float vb  = __shfl_xor_sync(0xffffffffu, b,   off);
                    float vb2 = __shfl_xor_sync(0xffffffffu, b2v, off);
                    int   vi  = __shfl_xor_sync(0xffffffffu, bi,  off);
                    if (vb < b) { b2v = fminf(b, vb2); b = vb; bi = vi; }
                    else if (vb > b) { b2v = fminf(b2v, vb); }
                    else { bi = min(bi, vi); b2v = vb; }
                }
                if (lc == 0) {
                    int s = row * 8 + wid;
                    float ob = sbest[s], ob2 = sb2[s];
                    int   oi = sidn[s];
                    if (b < ob)      { sbest[s] = b;  sb2[s] = fminf(ob, b2v);  sidn[s] = bi; }
                    else if (b > ob) {                sb2[s] = fminf(ob2, b);                 }
                    else             {                sb2[s] = ob;              sidn[s] = min(oi, bi); }
                }
            }
        }
        __syncthreads();
    }

    // ---- final per-row merge + flag ----
    if (t < MT) {
        float b  = sbest[t * 8];
        float bb = sb2  [t * 8];
        int   bi = sidn [t * 8];
#pragma unroll
        for (int x = 1; x < 8; x++) {
            float v  = sbest[t * 8 + x];
            float v2 = sb2  [t * 8 + x];
            int   vi = sidn [t * 8 + x];
            if (v < b) { bb = fminf(b, v2); b = v; bi = vi; }
            else if (v > b) { bb = fminf(bb, v); }
            else { bi = min(bi, vi); bb = v; }
        }
        srow[t] = bi;
        if (__fsub_rn(bb, b) < MARGIN) {
            int row = row0 + t;
            g_best[row] = ~0ULL;
            int p = atomicAdd(&g_flagcnt, 1);
            g_flagrows[p] = row;
        }
    }
    __syncthreads();

    // ---- gather: out[row] = emb[idx] (flagged rows fixed later) ----
    float4*       out4 = reinterpret_cast<float4*>(out + (size_t)row0 * DIMS);
    const float4* emb4 = reinterpret_cast<const float4*>(emb);
    for (int v = t; v < MT * (DIMS / 4); v += 256) {
        int r  = v >> 7;
        int c4 = v & 127;
        out4[(size_t)r * 128 + c4] = emb4[(size_t)srow[r] * 128 + c4];
    }
}

// ---------------------------------------------------------------------------
// Exact fallback: R2-identical ascending-k fmaf chains for flagged rows.
// Task = 128 rows x 64 codes (R12-proven shape)
// ---------------------------------------------------------------------------
__global__ __launch_bounds__(256)
void vq_exact_kernel(const float* __restrict__ z,
                     const float* __restrict__ emb) {
    __shared__ float Zs[16 * 128];
    __shared__ float Es[16 * 64];
    __shared__ int   rlist[128];

    const int t  = threadIdx.x;
    const int tx = t & 15;    // 4 codes each
    const int ty = t >> 4;    // 8 rows each
    const int lr = t >> 2;    // staging row 0..63 (and +64)
    const int dq = t & 3;

    int cnt = g_flagcnt;
    if (cnt <= 0) return;
    int tb = (cnt + 127) >> 7;
    int total = tb * 16;

    for (int task = blockIdx.x; task < total; task += gridDim.x) {
        int rb = task >> 4;
        int cg = task & 15;
        int c0 = cg * 64;

        __syncthreads();
        if (t < 128) {
            int j = rb * 128 + t;
            rlist[t] = g_flagrows[j < cnt ? j : cnt - 1];
        }
        __syncthreads();

        int rows[8]; float zn[8];
#pragma unroll
        for (int i = 0; i < 8; i++) {
            rows[i] = rlist[ty * 8 + i];
            zn[i] = g_znorm[rows[i]];
        }
        float en[4];
#pragma unroll
        for (int j = 0; j < 4; j++) en[j] = g_enorm[c0 + tx * 4 + j];

        float acc[8][4];
#pragma unroll
        for (int i = 0; i < 8; i++)
#pragma unroll
            for (int j = 0; j < 4; j++) acc[i][j] = 0.f;

        for (int c = 0; c < 32; c++) {       // 32 x 16-float chunks, R2 ordering
            const int k0 = c * 16;
            float4 za = *reinterpret_cast<const float4*>(
                z + (size_t)rlist[lr] * DIMS + k0 + dq * 4);
            float4 zb = *reinterpret_cast<const float4*>(
                z + (size_t)rlist[lr + 64] * DIMS + k0 + dq * 4);
            __syncthreads();
            Zs[(dq * 4 + 0) * 128 + lr] = za.x;
            Zs[(dq * 4 + 1) * 128 + lr] = za.y;
            Zs[(dq * 4 + 2) * 128 + lr] = za.z;
            Zs[(dq * 4 + 3) * 128 + lr] = za.w;
            Zs[(dq * 4 + 0) * 128 + lr + 64] = zb.x;
            Zs[(dq * 4 + 1) * 128 + lr + 64] = zb.y;
            Zs[(dq * 4 + 2) * 128 + lr + 64] = zb.z;
            Zs[(dq * 4 + 3) * 128 + lr + 64] = zb.w;
            if (t < 256) {   // stage E: 64 codes x 16 K = 256 float4
                int r = t >> 2, q = t & 3;
                float4 x = *reinterpret_cast<const float4*>(
                    emb + (size_t)(c0 + r) * DIMS + k0 + q * 4);
                Es[(q * 4 + 0) * 64 + r] = x.x;
                Es[(q * 4 + 1) * 64 + r] = x.y;
                Es[(q * 4 + 2) * 64 + r] = x.z;
                Es[(q * 4 + 3) * 64 + r] = x.w;
            }
            __syncthreads();

#pragma unroll
            for (int k = 0; k < 16; k++) {
                float zf[8], ef[4];
                *reinterpret_cast<float4*>(zf)     = *reinterpret_cast<float4*>(&Zs[k * 128 + ty * 8]);
                *reinterpret_cast<float4*>(zf + 4) = *reinterpret_cast<float4*>(&Zs[k * 128 + ty * 8 + 4]);
                *reinterpret_cast<float4*>(ef)     = *reinterpret_cast<float4*>(&Es[k * 64 + tx * 4]);
#pragma unroll
                for (int i = 0; i < 8; i++)
#pragma unroll
                    for (int j = 0; j < 4; j++)
                        acc[i][j] = fmaf(zf[i], ef[j], acc[i][j]);
            }
        }

        // score + per-thread argmin + cross-lane packed min (tie -> lowest idx)
#pragma unroll
        for (int i = 0; i < 8; i++) {
            float bb = 3.4e38f;
            int   bi = 0;
#pragma unroll
            for (int j = 0; j < 4; j++) {
                float s = __fsub_rn(__fadd_rn(zn[i], en[j]),
                                    __fmul_rn(2.0f, acc[i][j]));
                if (s < bb) { bb = s; bi = c0 + tx * 4 + j; }
            }
            unsigned long long pk =
                ((unsigned long long)__float_as_uint(bb) << 32) | (unsigned)bi;
#pragma unroll
            for (int off = 1; off <= 8; off <<= 1) {
                unsigned long long o = __shfl_xor_sync(0xffffffffu, pk, off);
                if (o < pk) pk = o;
            }
            if (tx == 0) atomicMin(&g_best[rows[i]], pk);
        }
    }
}

// ---------------------------------------------------------------------------
// Fixup gather for flagged rows
// ---------------------------------------------------------------------------
__global__ void vq_fix_kernel(const float* __restrict__ emb,
                              float* __restrict__ out) {
    int cnt = g_flagcnt;
    for (int j = blockIdx.x; j < cnt; j += gridDim.x) {
        int row = g_flagrows[j];
        unsigned idx = (unsigned)(g_best[row] & 0xffffffffu);
        const float4* src = reinterpret_cast<const float4*>(emb + (size_t)idx * DIMS);
        float4*       dst = reinterpret_cast<float4*>(out + (size_t)row * DIMS);
        for (int v = threadIdx.x; v < DIMS / 4; v += blockDim.x)
            dst[v] = src[v];
    }
}

// ---------------------------------------------------------------------------
// Launch
// ---------------------------------------------------------------------------
extern "C" void kernel_launch(void* const* d_in, const int* in_sizes, int n_in,
                              void* d_out, int out_size) {
    const float* z   = (const float*)d_in[0];   // [32,2048,512] fp32
    const float* emb = (const float*)d_in[1];   // [1024,512] fp32
    float* out = (float*)d_out;

    cudaFuncSetAttribute(vq_mma_kernel,
                         cudaFuncAttributeMaxDynamicSharedMemorySize, SM_DYN);

    econv_kernel<<<(CODES * 32 + 255) / 256, 256>>>(emb);   // also resets flagcnt
    zconv_kernel<<<(NROWS * 32 + 255) / 256, 256>>>(z);
    vq_mma_kernel<<<NROWS / MT, 256, SM_DYN>>>(emb, out);
    vq_exact_kernel<<<1024, 256>>>(z, emb);
    vq_fix_kernel<<<1024, 128>>>(emb, out);
}

// round 15
// speedup vs baseline: 1.0151x; 1.0016x over previous
#include <cuda_runtime.h>
#include <cuda_fp16.h>
#include <cstdint>
#include <cfloat>

// Problem constants
#define NROWS 65536   // 32 * 2048
#define DIMS  512
#define CODES 1024

#define MT   128      // rows per CTA (TC kernel)
#define NT2  256      // codes per tile
#define KC   32       // K floats per chunk (fp16: 16 u32 per row)
#define NCH  (DIMS / KC)     // 16 chunks
#define NTL  (CODES / NT2)   // 4 tiles

#define MARGIN 2.0e-4f       // ~13 sigma of fp16 score error

// Scratch (device globals — allocation is forbidden)
__device__ float g_enorm[CODES];
__device__ float g_znorm[NROWS];
__device__ int   g_flagcnt;
__device__ int   g_flagrows[NROWS];
__device__ unsigned long long g_best[NROWS];
__device__ uint32_t g_z16[NROWS * DIMS / 2];   // 64 MB fp16-packed z
__device__ uint32_t g_e16[CODES * DIMS / 2];   // 1 MB fp16-packed emb

// ---------------------------------------------------------------------------
// Helpers
// ---------------------------------------------------------------------------
__device__ __forceinline__ void mma_f16(float* c,
                                        uint32_t a0, uint32_t a1, uint32_t a2, uint32_t a3,
                                        uint32_t b0, uint32_t b1) {
    asm volatile(
        "mma.sync.aligned.m16n8k16.row.col.f32.f16.f16.f32 "
        "{%0,%1,%2,%3}, {%4,%5,%6,%7}, {%8,%9}, {%0,%1,%2,%3};"
        : "+f"(c[0]), "+f"(c[1]), "+f"(c[2]), "+f"(c[3])
        : "r"(a0), "r"(a1), "r"(a2), "r"(a3), "r"(b0), "r"(b1));
}

__device__ __forceinline__ void ldsm_x4(uint32_t* f, uint32_t addr) {
    asm volatile(
        "ldmatrix.sync.aligned.m8n8.x4.shared.b16 {%0,%1,%2,%3}, [%4];"
        : "=r"(f[0]), "=r"(f[1]), "=r"(f[2]), "=r"(f[3]) : "r"(addr));
}

// byte offset of the 16B group (row r, u32-group g) in a swizzled [rows][16]-u32 tile
__device__ __forceinline__ uint32_t swz_grp(int r, int g) {
    int xr = (r >> 1) & 3;
    return (uint32_t)(((r << 4) + (((g ^ xr) & 3) << 2)) << 2);
}

__device__ __forceinline__ uint32_t pack_h2(float lo, float hi) {
    __half2 p = __float22half2_rn(make_float2(lo, hi));   // .x -> low 16 bits
    return *reinterpret_cast<uint32_t*>(&p);
}

// ---------------------------------------------------------------------------
// Convert kernels: fp32 -> packed fp16 globals, fused fp64 norms (R12-proven)
// ---------------------------------------------------------------------------
__global__ void econv_kernel(const float* __restrict__ emb) {
    if (blockIdx.x == 0 && threadIdx.x == 0) g_flagcnt = 0;
    int warp = (blockIdx.x * blockDim.x + threadIdx.x) >> 5;
    int lane = threadIdx.x & 31;
    if (warp >= CODES) return;
    const float4* row = reinterpret_cast<const float4*>(emb + (size_t)warp * DIMS);
    double s = 0.0;
#pragma unroll
    for (int i = 0; i < 4; i++) {
        int j = lane + i * 32;
        float4 v = row[j];
        s += (double)v.x * v.x + (double)v.y * v.y
           + (double)v.z * v.z + (double)v.w * v.w;
        uint2 w = make_uint2(pack_h2(v.x, v.y), pack_h2(v.z, v.w));
        *reinterpret_cast<uint2*>(&g_e16[(size_t)warp * 256 + j * 2]) = w;
    }
#pragma unroll
    for (int off = 16; off > 0; off >>= 1)
        s += __shfl_xor_sync(0xffffffffu, s, off);
    if (lane == 0) g_enorm[warp] = (float)s;
}

__global__ void zconv_kernel(const float* __restrict__ z) {
    int warp = (blockIdx.x * blockDim.x + threadIdx.x) >> 5;
    int lane = threadIdx.x & 31;
    if (warp >= NROWS) return;
    const float4* row = reinterpret_cast<const float4*>(z + (size_t)warp * DIMS);
    double s = 0.0;
#pragma unroll
    for (int i = 0; i < 4; i++) {
        int j = lane + i * 32;
        float4 v = row[j];
        s += (double)v.x * v.x + (double)v.y * v.y
           + (double)v.z * v.z + (double)v.w * v.w;
        uint2 w = make_uint2(pack_h2(v.x, v.y), pack_h2(v.z, v.w));
        *reinterpret_cast<uint2*>(&g_z16[(size_t)warp * 256 + j * 2]) = w;
    }
#pragma unroll
    for (int off = 16; off > 0; off >>= 1)
        s += __shfl_xor_sync(0xffffffffu, s, off);
    if (lane == 0) g_znorm[warp] = (float)s;
}

// ---------------------------------------------------------------------------
// TC kernel: R12 configuration verbatim (local optimum at HMMA floor)
// fp16 mma.sync (k16), A resident, B dbuf, N-tile = 256, 512 threads
// ---------------------------------------------------------------------------
#define SM_A_BYTES (NCH * 8192)              // 131072
#define SM_DYN     (SM_A_BYTES + 2 * 16384)  // 163840

extern __shared__ uint32_t dsm[];

__global__ __launch_bounds__(512, 1)
void vq_mma_kernel(const float* __restrict__ emb,
                   float* __restrict__ out) {
    __shared__ float znr[128];
    __shared__ float sen[NT2];
    __shared__ float sbest[128 * 8];
    __shared__ float sb2  [128 * 8];
    __shared__ int   sidn [128 * 8];
    __shared__ int   srow [128];

    const int t    = threadIdx.x;
    const int lane = t & 31;
    const int wid  = t >> 5;
    const int row0 = blockIdx.x * MT;
    const int wm   = (wid & 1) * 64;
    const int wcol = wid >> 1;          // 0..7
    const int wn   = wcol * 32;
    const int lr4  = lane >> 2;
    const int lc   = lane & 3;

    const int m8 = lane >> 3, l7 = lane & 7;
    const int arow_off = ((m8 & 1) << 3) + l7;
    const int ag_off   = m8 >> 1;
    const int brow     = wn + ((m8 >> 1) << 3) + l7;
    const int bg_off   = m8 & 1;

    const uint32_t sAb = (uint32_t)__cvta_generic_to_shared(dsm);
    const uint32_t sBb = sAb + SM_A_BYTES;

    const int sr = t >> 2, sg = t & 3;
    const uint32_t stsA = swz_grp(sr, sg);
    const uint32_t stsB0 = swz_grp(sr, sg);
    const uint32_t stsB1 = swz_grp(sr + 128, sg);

    for (int i = t; i < 128 * 8; i += 512) {
        sbest[i] = FLT_MAX; sb2[i] = FLT_MAX; sidn[i] = 0;
    }
    if (t < 128) znr[t] = g_znorm[row0 + t];

    {
        const uint32_t* zsrc = &g_z16[(size_t)(row0 + sr) * 256 + sg * 4];
        char* sAc = reinterpret_cast<char*>(dsm);
#pragma unroll
        for (int c = 0; c < NCH; c++) {
            uint4 v = *reinterpret_cast<const uint4*>(zsrc + c * 16);
            *reinterpret_cast<uint4*>(sAc + c * 8192 + stsA) = v;
        }
    }
    __syncthreads();

    char* sBc = reinterpret_cast<char*>(dsm) + SM_A_BYTES;

    for (int nt = 0; nt < NTL; nt++) {
        const int n0 = nt * NT2;
        if (t < NT2 / 4)
            reinterpret_cast<float4*>(sen)[t] =
                reinterpret_cast<const float4*>(&g_enorm[n0])[t];

        float acc[4][4][4];
#pragma unroll
        for (int mi = 0; mi < 4; mi++)
#pragma unroll
            for (int nj = 0; nj < 4; nj++)
#pragma unroll
                for (int q = 0; q < 4; q++) acc[mi][nj][q] = 0.f;

        const uint32_t* bsrc0 = &g_e16[(size_t)(n0 + sr) * 256 + sg * 4];
        const uint32_t* bsrc1 = bsrc0 + 128 * 256;

        uint4 pb0 = *reinterpret_cast<const uint4*>(bsrc0);
        uint4 pb1 = *reinterpret_cast<const uint4*>(bsrc1);
        *reinterpret_cast<uint4*>(sBc + stsB0) = pb0;
        *reinterpret_cast<uint4*>(sBc + stsB1) = pb1;
        __syncthreads();

        for (int c = 0; c < NCH; c++) {
            const int cur = c & 1;
            if (c + 1 < NCH) {
                pb0 = *reinterpret_cast<const uint4*>(bsrc0 + (c + 1) * 16);
                pb1 = *reinterpret_cast<const uint4*>(bsrc1 + (c + 1) * 16);
            }

            const uint32_t bufA = sAb + c * 8192;
            const uint32_t bufB = sBb + cur * 16384;
#pragma unroll
            for (int ks = 0; ks < 2; ks++) {
                uint32_t B0[4], B1[4];
                ldsm_x4(B0, bufB + swz_grp(brow,      2 * ks + bg_off));
                ldsm_x4(B1, bufB + swz_grp(brow + 16, 2 * ks + bg_off));
#pragma unroll
                for (int mi = 0; mi < 4; mi++) {
                    uint32_t A[4];
                    ldsm_x4(A, bufA + swz_grp(wm + mi * 16 + arow_off, 2 * ks + ag_off));
                    mma_f16(acc[mi][0], A[0], A[1], A[2], A[3], B0[0], B0[1]);
                    mma_f16(acc[mi][1], A[0], A[1], A[2], A[3], B0[2], B0[3]);
                    mma_f16(acc[mi][2], A[0], A[1], A[2], A[3], B1[0], B1[1]);
                    mma_f16(acc[mi][3], A[0], A[1], A[2], A[3], B1[2], B1[3]);
                }
            }

            if (c + 1 < NCH) {
                char* nbuf = sBc + (cur ^ 1) * 16384;
                *reinterpret_cast<uint4*>(nbuf + stsB0) = pb0;
                *reinterpret_cast<uint4*>(nbuf + stsB1) = pb1;
            }
            __syncthreads();
        }

        // ---- epilogue: ref-rounding score + tile top-2 + smem merge ----
#pragma unroll
        for (int mi = 0; mi < 4; mi++) {
#pragma unroll
            for (int h = 0; h < 2; h++) {
                int row = wm + mi * 16 + lr4 + 8 * h;
                float znv = znr[row];
                float b = FLT_MAX, b2v = FLT_MAX;
                int   bi = 0;
#pragma unroll
                for (int nj = 0; nj < 4; nj++) {
                    int ce = wn + nj * 8 + 2 * lc;
                    float en0 = sen[ce], en1 = sen[ce + 1];
                    float s0 = __fsub_rn(__fadd_rn(znv, en0), __fmul_rn(2.0f, acc[mi][nj][h * 2]));
                    float s1 = __fsub_rn(__fadd_rn(znv, en1), __fmul_rn(2.0f, acc[mi][nj][h * 2 + 1]));
                    int cb = n0 + ce;
                    if (s0 < b) { b2v = b; b = s0; bi = cb; }
                    else if (s0 < b2v) b2v = s0;
                    if (s1 < b) { b2v = b; b = s1; bi = cb + 1; }
                    else if (s1 < b2v) b2v = s1;
                }
#pragma unroll
                for (int off = 1; off <= 2; off <<= 1) {
                    float vb  = __shfl_xor_sync(0xffffffffu, b,   off);
                    float vb2 = __shfl_xor_sync(0xffffffffu, b2v, off);
                    int   vi  = __shfl_xor_sync(0xffffffffu, bi,  off);
                    if (vb < b) { b2v = fminf(b, vb2); b = vb; bi = vi; }
                    else if (vb > b) { b2v = fminf(b2v, vb); }
                    else { bi = min(bi, vi); b2v = vb; }
                }
                if (lc == 0) {
                    int s = row * 8 + wcol;
                    float ob = sbest[s], ob2 = sb2[s];
                    int   oi = sidn[s];
                    if (b < ob)      { sbest[s] = b;  sb2[s] = fminf(ob, b2v);  sidn[s] = bi; }
                    else if (b > ob) {                sb2[s] = fminf(ob2, b);                 }
                    else             {                sb2[s] = ob;              sidn[s] = min(oi, bi); }
                }
            }
        }
        __syncthreads();
    }

    // ---- final per-row merge + flag ----
    if (t < 128) {
        float b  = sbest[t * 8];
        float bb = sb2  [t * 8];
        int   bi = sidn [t * 8];
#pragma unroll
        for (int x = 1; x < 8; x++) {
            float v  = sbest[t * 8 + x];
            float v2 = sb2  [t * 8 + x];
            int   vi = sidn [t * 8 + x];
            if (v < b) { bb = fminf(b, v2); b = v; bi = vi; }
            else if (v > b) { bb = fminf(bb, v); }
            else { bi = min(bi, vi); bb = v; }
        }
        srow[t] = bi;
        if (__fsub_rn(bb, b) < MARGIN) {
            int row = row0 + t;
            g_best[row] = ~0ULL;
            int p = atomicAdd(&g_flagcnt, 1);
            g_flagrows[p] = row;
        }
    }
    __syncthreads();

    // ---- gather ----
    float4*       out4 = reinterpret_cast<float4*>(out + (size_t)row0 * DIMS);
    const float4* emb4 = reinterpret_cast<const float4*>(emb);
    for (int v = t; v < 128 * (DIMS / 4); v += 512) {
        int r  = v >> 7;
        int c4 = v & 127;
        out4[(size_t)r * 128 + c4] = emb4[(size_t)srow[r] * 128 + c4];
    }
}

// ---------------------------------------------------------------------------
// Exact fallback: R2-identical ascending-k fmaf chains for flagged rows.
// Task = 64 rows x 64 codes -> ~320 tasks, 4x4 microtile (8k-FMA chain),
// ~60 regs -> 2+ blocks/SM so LDS latency hides across blocks.
// ---------------------------------------------------------------------------
__global__ __launch_bounds__(256)
void vq_exact_kernel(const float* __restrict__ z,
                     const float* __restrict__ emb) {
    __shared__ float Zs[16 * 64];
    __shared__ float Es[16 * 64];
    __shared__ int   rlist[64];

    const int t  = threadIdx.x;
    const int tx = t & 15;    // 4 codes each
    const int ty = t >> 4;    // 4 rows each (16 groups x 4 = 64 rows)

    int cnt = g_flagcnt;
    if (cnt <= 0) return;
    int tb = (cnt + 63) >> 6;
    int total = tb * 16;      // 16 code-groups of 64

    for (int task = blockIdx.x; task < total; task += gridDim.x) {
        int rb = task >> 4;
        int cg = task & 15;
        int c0 = cg * 64;

        __syncthreads();
        if (t < 64) {
            int j = rb * 64 + t;
            rlist[t] = g_flagrows[j < cnt ? j : cnt - 1];
        }
        __syncthreads();

        int rows[4]; float zn[4];
#pragma unroll
        for (int i = 0; i < 4; i++) {
            rows[i] = rlist[ty * 4 + i];
            zn[i] = g_znorm[rows[i]];
        }
        float en[4];
#pragma unroll
        for (int j = 0; j < 4; j++) en[j] = g_enorm[c0 + tx * 4 + j];

        float acc[4][4];
#pragma unroll
        for (int i = 0; i < 4; i++)
#pragma unroll
            for (int j = 0; j < 4; j++) acc[i][j] = 0.f;

        for (int c = 0; c < 32; c++) {       // 32 x 16-float chunks, R2 ordering
            const int k0 = c * 16;
            // stage Z: 64 rows x 16 K = 256 float4, 1/thread
            int r = t >> 2, q = t & 3;
            float4 zx = *reinterpret_cast<const float4*>(
                z + (size_t)rlist[r] * DIMS + k0 + q * 4);
            float4 ex = *reinterpret_cast<const float4*>(
                emb + (size_t)(c0 + r) * DIMS + k0 + q * 4);
            __syncthreads();
            Zs[(q * 4 + 0) * 64 + r] = zx.x;
            Zs[(q * 4 + 1) * 64 + r] = zx.y;
            Zs[(q * 4 + 2) * 64 + r] = zx.z;
            Zs[(q * 4 + 3) * 64 + r] = zx.w;
            Es[(q * 4 + 0) * 64 + r] = ex.x;
            Es[(q * 4 + 1) * 64 + r] = ex.y;
            Es[(q * 4 + 2) * 64 + r] = ex.z;
            Es[(q * 4 + 3) * 64 + r] = ex.w;
            __syncthreads();

#pragma unroll
            for (int k = 0; k < 16; k++) {
                float zf[4], ef[4];
                *reinterpret_cast<float4*>(zf) = *reinterpret_cast<float4*>(&Zs[k * 64 + ty * 4]);
                *reinterpret_cast<float4*>(ef) = *reinterpret_cast<float4*>(&Es[k * 64 + tx * 4]);
#pragma unroll
                for (int i = 0; i < 4; i++)
#pragma unroll
                    for (int j = 0; j < 4; j++)
                        acc[i][j] = fmaf(zf[i], ef[j], acc[i][j]);
            }
        }

        // score + per-thread argmin + cross-lane packed min (tie -> lowest idx)
#pragma unroll
        for (int i = 0; i < 4; i++) {
            float bb = 3.4e38f;
            int   bi = 0;
#pragma unroll
            for (int j = 0; j < 4; j++) {
                float s = __fsub_rn(__fadd_rn(zn[i], en[j]),
                                    __fmul_rn(2.0f, acc[i][j]));
                if (s < bb) { bb = s; bi = c0 + tx * 4 + j; }
            }
            unsigned long long pk =
                ((unsigned long long)__float_as_uint(bb) << 32) | (unsigned)bi;
#pragma unroll
            for (int off = 1; off <= 8; off <<= 1) {
                unsigned long long o = __shfl_xor_sync(0xffffffffu, pk, off);
                if (o < pk) pk = o;
            }
            if (tx == 0) atomicMin(&g_best[rows[i]], pk);
        }
    }
}

// ---------------------------------------------------------------------------
// Fixup gather for flagged rows
// ---------------------------------------------------------------------------
__global__ void vq_fix_kernel(const float* __restrict__ emb,
                              float* __restrict__ out) {
    int cnt = g_flagcnt;
    for (int j = blockIdx.x; j < cnt; j += gridDim.x) {
        int row = g_flagrows[j];
        unsigned idx = (unsigned)(g_best[row] & 0xffffffffu);
        const float4* src = reinterpret_cast<const float4*>(emb + (size_t)idx * DIMS);
        float4*       dst = reinterpret_cast<float4*>(out + (size_t)row * DIMS);
        for (int v = threadIdx.x; v < DIMS / 4; v += blockDim.x)
            dst[v] = src[v];
    }
}

// ---------------------------------------------------------------------------
// Launch
// ---------------------------------------------------------------------------
extern "C" void kernel_launch(void* const* d_in, const int* in_sizes, int n_in,
                              void* d_out, int out_size) {
    const float* z   = (const float*)d_in[0];   // [32,2048,512] fp32
    const float* emb = (const float*)d_in[1];   // [1024,512] fp32
    float* out = (float*)d_out;

    cudaFuncSetAttribute(vq_mma_kernel,
                         cudaFuncAttributeMaxDynamicSharedMemorySize, SM_DYN);

    econv_kernel<<<(CODES * 32 + 255) / 256, 256>>>(emb);   // also resets flagcnt
    zconv_kernel<<<(NROWS * 32 + 255) / 256, 256>>>(z);
    vq_mma_kernel<<<NROWS / MT, 512, SM_DYN>>>(emb, out);
    vq_exact_kernel<<<1024, 256>>>(z, emb);
    vq_fix_kernel<<<1024, 128>>>(emb, out);
}

// round 17
// speedup vs baseline: 1.0408x; 1.0253x over previous
#include <cuda_runtime.h>
#include <cuda_fp16.h>
#include <cstdint>
#include <cfloat>

// Problem constants
#define NROWS 65536   // 32 * 2048
#define DIMS  512
#define CODES 1024

#define MT   128      // rows per CTA (TC kernel)
#define NT2  256      // codes per tile
#define KC   32       // K floats per chunk (fp16: 16 u32 per row)
#define NCH  (DIMS / KC)     // 16 chunks
#define NTL  (CODES / NT2)   // 4 tiles

#define MARGIN 2.0e-4f       // empirically validated safety margin (R9-R15: rel_err 0.0)

// Scratch (device globals — allocation is forbidden)
__device__ float g_enorm[CODES];
__device__ float g_znorm[NROWS];
__device__ int   g_flagcnt;
__device__ int   g_flagrows[NROWS];
__device__ unsigned long long g_best[NROWS];
__device__ uint32_t g_z16[NROWS * DIMS / 2];   // 64 MB fp16-packed z
__device__ uint32_t g_e16[CODES * DIMS / 2];   // 1 MB fp16-packed emb

// ---------------------------------------------------------------------------
// Helpers
// ---------------------------------------------------------------------------
__device__ __forceinline__ void mma_f16(float* c,
                                        uint32_t a0, uint32_t a1, uint32_t a2, uint32_t a3,
                                        uint32_t b0, uint32_t b1) {
    asm volatile(
        "mma.sync.aligned.m16n8k16.row.col.f32.f16.f16.f32 "
        "{%0,%1,%2,%3}, {%4,%5,%6,%7}, {%8,%9}, {%0,%1,%2,%3};"
        : "+f"(c[0]), "+f"(c[1]), "+f"(c[2]), "+f"(c[3])
        : "r"(a0), "r"(a1), "r"(a2), "r"(a3), "r"(b0), "r"(b1));
}

__device__ __forceinline__ void ldsm_x4(uint32_t* f, uint32_t addr) {
    asm volatile(
        "ldmatrix.sync.aligned.m8n8.x4.shared.b16 {%0,%1,%2,%3}, [%4];"
        : "=r"(f[0]), "=r"(f[1]), "=r"(f[2]), "=r"(f[3]) : "r"(addr));
}

// byte offset of the 16B group (row r, u32-group g) in a swizzled [rows][16]-u32 tile
__device__ __forceinline__ uint32_t swz_grp(int r, int g) {
    int xr = (r >> 1) & 3;
    return (uint32_t)(((r << 4) + (((g ^ xr) & 3) << 2)) << 2);
}

__device__ __forceinline__ uint32_t pack_h2(float lo, float hi) {
    __half2 p = __float22half2_rn(make_float2(lo, hi));   // .x -> low 16 bits
    return *reinterpret_cast<uint32_t*>(&p);
}

// ---------------------------------------------------------------------------
// Convert kernels: fp32 -> packed fp16 globals, fused fp64 norms (R12-proven)
// ---------------------------------------------------------------------------
__global__ void econv_kernel(const float* __restrict__ emb) {
    if (blockIdx.x == 0 && threadIdx.x == 0) g_flagcnt = 0;
    int warp = (blockIdx.x * blockDim.x + threadIdx.x) >> 5;
    int lane = threadIdx.x & 31;
    if (warp >= CODES) return;
    const float4* row = reinterpret_cast<const float4*>(emb + (size_t)warp * DIMS);
    double s = 0.0;
#pragma unroll
    for (int i = 0; i < 4; i++) {
        int j = lane + i * 32;
        float4 v = row[j];
        s += (double)v.x * v.x + (double)v.y * v.y
           + (double)v.z * v.z + (double)v.w * v.w;
        uint2 w = make_uint2(pack_h2(v.x, v.y), pack_h2(v.z, v.w));
        *reinterpret_cast<uint2*>(&g_e16[(size_t)warp * 256 + j * 2]) = w;
    }
#pragma unroll
    for (int off = 16; off > 0; off >>= 1)
        s += __shfl_xor_sync(0xffffffffu, s, off);
    if (lane == 0) g_enorm[warp] = (float)s;
}

__global__ void zconv_kernel(const float* __restrict__ z) {
    int warp = (blockIdx.x * blockDim.x + threadIdx.x) >> 5;
    int lane = threadIdx.x & 31;
    if (warp >= NROWS) return;
    const float4* row = reinterpret_cast<const float4*>(z + (size_t)warp * DIMS);
    double s = 0.0;
#pragma unroll
    for (int i = 0; i < 4; i++) {
        int j = lane + i * 32;
        float4 v = row[j];
        s += (double)v.x * v.x + (double)v.y * v.y
           + (double)v.z * v.z + (double)v.w * v.w;
        uint2 w = make_uint2(pack_h2(v.x, v.y), pack_h2(v.z, v.w));
        *reinterpret_cast<uint2*>(&g_z16[(size_t)warp * 256 + j * 2]) = w;
    }
#pragma unroll
    for (int off = 16; off > 0; off >>= 1)
        s += __shfl_xor_sync(0xffffffffu, s, off);
    if (lane == 0) g_znorm[warp] = (float)s;
}

// ---------------------------------------------------------------------------
// TC kernel: R12 configuration verbatim (local optimum at HMMA floor)
// fp16 mma.sync (k16), A resident, B dbuf, N-tile = 256, 512 threads
// ---------------------------------------------------------------------------
#define SM_A_BYTES (NCH * 8192)              // 131072
#define SM_DYN     (SM_A_BYTES + 2 * 16384)  // 163840

extern __shared__ uint32_t dsm[];

__global__ __launch_bounds__(512, 1)
void vq_mma_kernel(const float* __restrict__ emb,
                   float* __restrict__ out) {
    __shared__ float znr[128];
    __shared__ float sen[NT2];
    __shared__ float sbest[128 * 8];
    __shared__ float sb2  [128 * 8];
    __shared__ int   sidn [128 * 8];
    __shared__ int   srow [128];

    const int t    = threadIdx.x;
    const int lane = t & 31;
    const int wid  = t >> 5;
    const int row0 = blockIdx.x * MT;
    const int wm   = (wid & 1) * 64;
    const int wcol = wid >> 1;          // 0..7
    const int wn   = wcol * 32;
    const int lr4  = lane >> 2;
    const int lc   = lane & 3;

    const int m8 = lane >> 3, l7 = lane & 7;
    const int arow_off = ((m8 & 1) << 3) + l7;
    const int ag_off   = m8 >> 1;
    const int brow     = wn + ((m8 >> 1) << 3) + l7;
    const int bg_off   = m8 & 1;

    const uint32_t sAb = (uint32_t)__cvta_generic_to_shared(dsm);
    const uint32_t sBb = sAb + SM_A_BYTES;

    const int sr = t >> 2, sg = t & 3;
    const uint32_t stsA = swz_grp(sr, sg);
    const uint32_t stsB0 = swz_grp(sr, sg);
    const uint32_t stsB1 = swz_grp(sr + 128, sg);

    for (int i = t; i < 128 * 8; i += 512) {
        sbest[i] = FLT_MAX; sb2[i] = FLT_MAX; sidn[i] = 0;
    }
    if (t < 128) znr[t] = g_znorm[row0 + t];

    {
        const uint32_t* zsrc = &g_z16[(size_t)(row0 + sr) * 256 + sg * 4];
        char* sAc = reinterpret_cast<char*>(dsm);
#pragma unroll
        for (int c = 0; c < NCH; c++) {
            uint4 v = *reinterpret_cast<const uint4*>(zsrc + c * 16);
            *reinterpret_cast<uint4*>(sAc + c * 8192 + stsA) = v;
        }
    }
    __syncthreads();

    char* sBc = reinterpret_cast<char*>(dsm) + SM_A_BYTES;

    for (int nt = 0; nt < NTL; nt++) {
        const int n0 = nt * NT2;
        if (t < NT2 / 4)
            reinterpret_cast<float4*>(sen)[t] =
                reinterpret_cast<const float4*>(&g_enorm[n0])[t];

        float acc[4][4][4];
#pragma unroll
        for (int mi = 0; mi < 4; mi++)
#pragma unroll
            for (int nj = 0; nj < 4; nj++)
#pragma unroll
                for (int q = 0; q < 4; q++) acc[mi][nj][q] = 0.f;

        const uint32_t* bsrc0 = &g_e16[(size_t)(n0 + sr) * 256 + sg * 4];
        const uint32_t* bsrc1 = bsrc0 + 128 * 256;

        uint4 pb0 = *reinterpret_cast<const uint4*>(bsrc0);
        uint4 pb1 = *reinterpret_cast<const uint4*>(bsrc1);
        *reinterpret_cast<uint4*>(sBc + stsB0) = pb0;
        *reinterpret_cast<uint4*>(sBc + stsB1) = pb1;
        __syncthreads();

        for (int c = 0; c < NCH; c++) {
            const int cur = c & 1;
            if (c + 1 < NCH) {
                pb0 = *reinterpret_cast<const uint4*>(bsrc0 + (c + 1) * 16);
                pb1 = *reinterpret_cast<const uint4*>(bsrc1 + (c + 1) * 16);
            }

            const uint32_t bufA = sAb + c * 8192;
            const uint32_t bufB = sBb + cur * 16384;
#pragma unroll
            for (int ks = 0; ks < 2; ks++) {
                uint32_t B0[4], B1[4];
                ldsm_x4(B0, bufB + swz_grp(brow,      2 * ks + bg_off));
                ldsm_x4(B1, bufB + swz_grp(brow + 16, 2 * ks + bg_off));
#pragma unroll
                for (int mi = 0; mi < 4; mi++) {
                    uint32_t A[4];
                    ldsm_x4(A, bufA + swz_grp(wm + mi * 16 + arow_off, 2 * ks + ag_off));
                    mma_f16(acc[mi][0], A[0], A[1], A[2], A[3], B0[0], B0[1]);
                    mma_f16(acc[mi][1], A[0], A[1], A[2], A[3], B0[2], B0[3]);
                    mma_f16(acc[mi][2], A[0], A[1], A[2], A[3], B1[0], B1[1]);
                    mma_f16(acc[mi][3], A[0], A[1], A[2], A[3], B1[2], B1[3]);
                }
            }

            if (c + 1 < NCH) {
                char* nbuf = sBc + (cur ^ 1) * 16384;
                *reinterpret_cast<uint4*>(nbuf + stsB0) = pb0;
                *reinterpret_cast<uint4*>(nbuf + stsB1) = pb1;
            }
            __syncthreads();
        }

        // ---- epilogue: ref-rounding score + tile top-2 + smem merge ----
#pragma unroll
        for (int mi = 0; mi < 4; mi++) {
#pragma unroll
            for (int h = 0; h < 2; h++) {
                int row = wm + mi * 16 + lr4 + 8 * h;
                float znv = znr[row];
                float b = FLT_MAX, b2v = FLT_MAX;
                int   bi = 0;
#pragma unroll
                for (int nj = 0; nj < 4; nj++) {
                    int ce = wn + nj * 8 + 2 * lc;
                    float en0 = sen[ce], en1 = sen[ce + 1];
                    float s0 = __fsub_rn(__fadd_rn(znv, en0), __fmul_rn(2.0f, acc[mi][nj][h * 2]));
                    float s1 = __fsub_rn(__fadd_rn(znv, en1), __fmul_rn(2.0f, acc[mi][nj][h * 2 + 1]));
                    int cb = n0 + ce;
                    if (s0 < b) { b2v = b; b = s0; bi = cb; }
                    else if (s0 < b2v) b2v = s0;
                    if (s1 < b) { b2v = b; b = s1; bi = cb + 1; }
                    else if (s1 < b2v) b2v = s1;
                }
#pragma unroll
                for (int off = 1; off <= 2; off <<= 1) {
                    float vb  = __shfl_xor_sync(0xffffffffu, b,   off);
                    float vb2 = __shfl_xor_sync(0xffffffffu, b2v, off);
                    int   vi  = __shfl_xor_sync(0xffffffffu, bi,  off);
                    if (vb < b) { b2v = fminf(b, vb2); b = vb; bi = vi; }
                    else if (vb > b) { b2v = fminf(b2v, vb); }
                    else { bi = min(bi, vi); b2v = vb; }
                }
                if (lc == 0) {
                    int s = row * 8 + wcol;
                    float ob = sbest[s], ob2 = sb2[s];
                    int   oi = sidn[s];
                    if (b < ob)      { sbest[s] = b;  sb2[s] = fminf(ob, b2v);  sidn[s] = bi; }
                    else if (b > ob) {                sb2[s] = fminf(ob2, b);                 }
                    else             {                sb2[s] = ob;              sidn[s] = min(oi, bi); }
                }
            }
        }
        __syncthreads();
    }

    // ---- final per-row merge + flag ----
    if (t < 128) {
        float b  = sbest[t * 8];
        float bb = sb2  [t * 8];
        int   bi = sidn [t * 8];
#pragma unroll
        for (int x = 1; x < 8; x++) {
            float v  = sbest[t * 8 + x];
            float v2 = sb2  [t * 8 + x];
            int   vi = sidn [t * 8 + x];
            if (v < b) { bb = fminf(b, v2); b = v; bi = vi; }
            else if (v > b) { bb = fminf(bb, v); }
            else { bi = min(bi, vi); bb = v; }
        }
        srow[t] = bi;
        if (__fsub_rn(bb, b) < MARGIN) {
            int row = row0 + t;
            g_best[row] = ~0ULL;
            int p = atomicAdd(&g_flagcnt, 1);
            g_flagrows[p] = row;
        }
    }
    __syncthreads();

    // ---- gather ----
    float4*       out4 = reinterpret_cast<float4*>(out + (size_t)row0 * DIMS);
    const float4* emb4 = reinterpret_cast<const float4*>(emb);
    for (int v = t; v < 128 * (DIMS / 4); v += 512) {
        int r  = v >> 7;
        int c4 = v & 127;
        out4[(size_t)r * 128 + c4] = emb4[(size_t)srow[r] * 128 + c4];
    }
}

// ---------------------------------------------------------------------------
// Exact fallback: R2-identical ascending-k fmaf chains for flagged rows.
// Task = 128 rows x 64 codes (R12-proven optimum shape)
// ---------------------------------------------------------------------------
__global__ __launch_bounds__(256)
void vq_exact_kernel(const float* __restrict__ z,
                     const float* __restrict__ emb) {
    __shared__ float Zs[16 * 128];
    __shared__ float Es[16 * 64];
    __shared__ int   rlist[128];

    const int t  = threadIdx.x;
    const int tx = t & 15;    // 4 codes each
    const int ty = t >> 4;    // 8 rows each
    const int lr = t >> 2;    // staging row 0..63 (and +64)
    const int dq = t & 3;

    int cnt = g_flagcnt;
    if (cnt <= 0) return;
    int tb = (cnt + 127) >> 7;
    int total = tb * 16;

    for (int task = blockIdx.x; task < total; task += gridDim.x) {
        int rb = task >> 4;
        int cg = task & 15;
        int c0 = cg * 64;

        __syncthreads();
        if (t < 128) {
            int j = rb * 128 + t;
            rlist[t] = g_flagrows[j < cnt ? j : cnt - 1];
        }
        __syncthreads();

        int rows[8]; float zn[8];
#pragma unroll
        for (int i = 0; i < 8; i++) {
            rows[i] = rlist[ty * 8 + i];
            zn[i] = g_znorm[rows[i]];
        }
        float en[4];
#pragma unroll
        for (int j = 0; j < 4; j++) en[j] = g_enorm[c0 + tx * 4 + j];

        float acc[8][4];
#pragma unroll
        for (int i = 0; i < 8; i++)
#pragma unroll
            for (int j = 0; j < 4; j++) acc[i][j] = 0.f;

        for (int c = 0; c < 32; c++) {       // 32 x 16-float chunks, R2 ordering
            const int k0 = c * 16;
            float4 za = *reinterpret_cast<const float4*>(
                z + (size_t)rlist[lr] * DIMS + k0 + dq * 4);
            float4 zb = *reinterpret_cast<const float4*>(
                z + (size_t)rlist[lr + 64] * DIMS + k0 + dq * 4);
            __syncthreads();
            Zs[(dq * 4 + 0) * 128 + lr] = za.x;
            Zs[(dq * 4 + 1) * 128 + lr] = za.y;
            Zs[(dq * 4 + 2) * 128 + lr] = za.z;
            Zs[(dq * 4 + 3) * 128 + lr] = za.w;
            Zs[(dq * 4 + 0) * 128 + lr + 64] = zb.x;
            Zs[(dq * 4 + 1) * 128 + lr + 64] = zb.y;
            Zs[(dq * 4 + 2) * 128 + lr + 64] = zb.z;
            Zs[(dq * 4 + 3) * 128 + lr + 64] = zb.w;
            if (t < 256) {   // stage E: 64 codes x 16 K = 256 float4
                int r = t >> 2, q = t & 3;
                float4 x = *reinterpret_cast<const float4*>(
                    emb + (size_t)(c0 + r) * DIMS + k0 + q * 4);
                Es[(q * 4 + 0) * 64 + r] = x.x;
                Es[(q * 4 + 1) * 64 + r] = x.y;
                Es[(q * 4 + 2) * 64 + r] = x.z;
                Es[(q * 4 + 3) * 64 + r] = x.w;
            }
            __syncthreads();

#pragma unroll
            for (int k = 0; k < 16; k++) {
                float zf[8], ef[4];
                *reinterpret_cast<float4*>(zf)     = *reinterpret_cast<float4*>(&Zs[k * 128 + ty * 8]);
                *reinterpret_cast<float4*>(zf + 4) = *reinterpret_cast<float4*>(&Zs[k * 128 + ty * 8 + 4]);
                *reinterpret_cast<float4*>(ef)     = *reinterpret_cast<float4*>(&Es[k * 64 + tx * 4]);
#pragma unroll
                for (int i = 0; i < 8; i++)
#pragma unroll
                    for (int j = 0; j < 4; j++)
                        acc[i][j] = fmaf(zf[i], ef[j], acc[i][j]);
            }
        }

        // score + per-thread argmin + cross-lane packed min (tie -> lowest idx)
#pragma unroll
        for (int i = 0; i < 8; i++) {
            float bb = 3.4e38f;
            int   bi = 0;
#pragma unroll
            for (int j = 0; j < 4; j++) {
                float s = __fsub_rn(__fadd_rn(zn[i], en[j]),
                                    __fmul_rn(2.0f, acc[i][j]));
                if (s < bb) { bb = s; bi = c0 + tx * 4 + j; }
            }
            unsigned long long pk =
                ((unsigned long long)__float_as_uint(bb) << 32) | (unsigned)bi;
#pragma unroll
            for (int off = 1; off <= 8; off <<= 1) {
                unsigned long long o = __shfl_xor_sync(0xffffffffu, pk, off);
                if (o < pk) pk = o;
            }
            if (tx == 0) atomicMin(&g_best[rows[i]], pk);
        }
    }
}

// ---------------------------------------------------------------------------
// Fixup gather for flagged rows
// ---------------------------------------------------------------------------
__global__ void vq_fix_kernel(const float* __restrict__ emb,
                              float* __restrict__ out) {
    int cnt = g_flagcnt;
    for (int j = blockIdx.x; j < cnt; j += gridDim.x) {
        int row = g_flagrows[j];
        unsigned idx = (unsigned)(g_best[row] & 0xffffffffu);
        const float4* src = reinterpret_cast<const float4*>(emb + (size_t)idx * DIMS);
        float4*       dst = reinterpret_cast<float4*>(out + (size_t)row * DIMS);
        for (int v = threadIdx.x; v < DIMS / 4; v += blockDim.x)
            dst[v] = src[v];
    }
}

// ---------------------------------------------------------------------------
// Launch
// ---------------------------------------------------------------------------
extern "C" void kernel_launch(void* const* d_in, const int* in_sizes, int n_in,
                              void* d_out, int out_size) {
    const float* z   = (const float*)d_in[0];   // [32,2048,512] fp32
    const float* emb = (const float*)d_in[1];   // [1024,512] fp32
    float* out = (float*)d_out;

    cudaFuncSetAttribute(vq_mma_kernel,
                         cudaFuncAttributeMaxDynamicSharedMemorySize, SM_DYN);

    econv_kernel<<<(CODES * 32 + 255) / 256, 256>>>(emb);   // also resets flagcnt
    zconv_kernel<<<(NROWS * 32 + 255) / 256, 256>>>(z);
    vq_mma_kernel<<<NROWS / MT, 512, SM_DYN>>>(emb, out);
    vq_exact_kernel<<<1024, 256>>>(z, emb);
    vq_fix_kernel<<<1024, 128>>>(emb, out);
}